// round 7
// baseline (speedup 1.0000x reference)
#include <cuda_runtime.h>

#define NN 100000
#define NE 1600000
#define FI 256
#define HD 32
#define AD 64
#define PD 512

// Scratch: __device__ globals referenced DIRECTLY by kernels.
__device__ float g_buf1[NN * HD];
__device__ float g_buf2[NN * HD];
__device__ float g_deg[NN];
__device__ float g_dinv[NN];

// ---------------------------------------------------------------------------
__global__ void k_zerodeg() {
    int i = blockIdx.x * blockDim.x + threadIdx.x;
    if (i < NN) g_deg[i] = 0.0f;
}

// edge_index is int32 (JAX demotes int64 -> int32 without x64 mode).
__global__ void k_deg(const int* __restrict__ dst) {
    int i = blockIdx.x * blockDim.x + threadIdx.x;
    if (i < NE) atomicAdd(&g_deg[dst[i]], 1.0f);
}

__global__ void k_dinv() {
    int i = blockIdx.x * blockDim.x + threadIdx.x;
    if (i < NN) g_dinv[i] = rsqrtf(g_deg[i] + 1.0f);  // +1 = self loop
}

// ---------------------------------------------------------------------------
// GEMM1: g_buf1 = features @ W1   ([100k,256] x [256,32])
// W1 in 32KB static smem; features streamed via float4 warp broadcasts.
// ---------------------------------------------------------------------------
__global__ void __launch_bounds__(256) k_gemm1(const float* __restrict__ feat,
                                               const float* __restrict__ W1) {
    __shared__ float sW[FI * HD];  // 8192 floats = 32KB
    int t = threadIdx.x;
#pragma unroll
    for (int i = 0; i < FI * HD / 256; i++) sW[t + i * 256] = W1[t + i * 256];
    __syncthreads();

    int c = t & 31, rg = t >> 5;  // rg constant within a warp
    long long row0 = (long long)blockIdx.x * 32;
    const float* f0 = feat + (row0 + rg) * FI;

    float a0 = 0.f, a1 = 0.f, a2 = 0.f, a3 = 0.f;
#pragma unroll 4
    for (int k = 0; k < FI; k += 4) {
        float4 fa = __ldg((const float4*)(f0 + k));
        float4 fb = __ldg((const float4*)(f0 + 8 * FI + k));
        float4 fc = __ldg((const float4*)(f0 + 16 * FI + k));
        float4 fd = __ldg((const float4*)(f0 + 24 * FI + k));
        float w0 = sW[(k + 0) * HD + c];
        float w1 = sW[(k + 1) * HD + c];
        float w2 = sW[(k + 2) * HD + c];
        float w3 = sW[(k + 3) * HD + c];
        a0 += fa.x * w0 + fa.y * w1 + fa.z * w2 + fa.w * w3;
        a1 += fb.x * w0 + fb.y * w1 + fb.z * w2 + fb.w * w3;
        a2 += fc.x * w0 + fc.y * w1 + fc.z * w2 + fc.w * w3;
        a3 += fd.x * w0 + fd.y * w1 + fd.z * w2 + fd.w * w3;
    }
    float* o = g_buf1 + row0 * HD;
    o[(rg) * HD + c] = a0;
    o[(rg + 8) * HD + c] = a1;
    o[(rg + 16) * HD + c] = a2;
    o[(rg + 24) * HD + c] = a3;
}

// ---------------------------------------------------------------------------
// Self-loop init: agg[i][:] = x[i][:] * dinv[i]^2
// DIR=0: x=g_buf1, agg=g_buf2.  DIR=1: x=g_buf2, agg=g_buf1.
// ---------------------------------------------------------------------------
template <int DIR>
__global__ void k_selfinit() {
    const float* x = DIR ? g_buf2 : g_buf1;
    float* agg = DIR ? g_buf1 : g_buf2;
    int i = blockIdx.x * blockDim.x + threadIdx.x;
    if (i < NN * HD) {
        float d = g_dinv[i >> 5];
        agg[i] = x[i] * d * d;
    }
}

// ---------------------------------------------------------------------------
// Edge scatter: one warp per edge, lane = feature.
// agg[dst][lane] += x[src][lane] * dinv[src]*dinv[dst]
// ---------------------------------------------------------------------------
template <int DIR>
__global__ void k_edge(const int* __restrict__ src, const int* __restrict__ dst) {
    const float* x = DIR ? g_buf2 : g_buf1;
    float* agg = DIR ? g_buf1 : g_buf2;
    int gt = blockIdx.x * blockDim.x + threadIdx.x;
    int e = gt >> 5;
    if (e >= NE) return;
    int lane = threadIdx.x & 31;
    int s = src[e];
    int d = dst[e];
    float nrm = g_dinv[s] * g_dinv[d];
    float v = x[s * HD + lane] * nrm;
    atomicAdd(&agg[d * HD + lane], v);
}

// ---------------------------------------------------------------------------
// out = relu(agg + b).  DIR=0: g_buf2 -> g_buf1.  DIR=1: g_buf1 -> g_buf2.
// ---------------------------------------------------------------------------
template <int DIR>
__global__ void k_biasrelu(const float* __restrict__ b) {
    const float* agg = DIR ? g_buf1 : g_buf2;
    float* out = DIR ? g_buf2 : g_buf1;
    int i = blockIdx.x * blockDim.x + threadIdx.x;
    if (i < NN * HD) out[i] = fmaxf(agg[i] + b[i & 31], 0.f);
}

// ---------------------------------------------------------------------------
// GEMM2: g_buf2 = g_buf1 @ W2   ([100k,32] x [32,32]), 64 rows per block
// ---------------------------------------------------------------------------
__global__ void __launch_bounds__(256) k_gemm2(const float* __restrict__ W2) {
    __shared__ float sW[HD * HD];   // 4KB
    __shared__ float sH[64 * 33];   // 8.25KB
    int t = threadIdx.x;
    for (int i = t; i < HD * HD; i += 256) sW[i] = W2[i];
    int row0 = blockIdx.x * 64;
    for (int i = t; i < 64 * 32; i += 256) {
        int r = i >> 5, c = i & 31;
        int gr = row0 + r;
        sH[r * 33 + c] = (gr < NN) ? g_buf1[gr * HD + c] : 0.f;
    }
    __syncthreads();
    int c = t & 31, rg = t >> 5;
    float acc[8];
#pragma unroll
    for (int i = 0; i < 8; i++) acc[i] = 0.f;
#pragma unroll
    for (int k = 0; k < HD; k++) {
        float w = sW[k * HD + c];
#pragma unroll
        for (int i = 0; i < 8; i++) acc[i] += sH[(rg + 8 * i) * 33 + k] * w;
    }
#pragma unroll
    for (int i = 0; i < 8; i++) {
        int gr = row0 + rg + 8 * i;
        if (gr < NN) g_buf2[gr * HD + c] = acc[i];
    }
}

// ---------------------------------------------------------------------------
// Fused heads, 16-node tile (static smem 41.3KB):
//   p1 = relu(h@pW1+pb1) [16,512] in SMEM  -> policy = p1@pW2+pb2 [16,64]
//   v1 = relu(h@vW1+vb1) [16,512] in SMEM  -> value  = v1@vW2+vb2 [16,1]
// h read from g_buf2.
// ---------------------------------------------------------------------------
__global__ void __launch_bounds__(256) k_head(
    const float* __restrict__ pW1, const float* __restrict__ pb1,
    const float* __restrict__ pW2, const float* __restrict__ pb2,
    const float* __restrict__ vW1, const float* __restrict__ vb1,
    const float* __restrict__ vW2, const float* __restrict__ vb2,
    float* __restrict__ out) {
    __shared__ float sH[16 * 33];   // 2112 floats
    __shared__ float sP[16 * 513];  // 8208 floats
    const int t = threadIdx.x;
    const int n0 = blockIdx.x * 16;

    for (int i = t; i < 16 * 32; i += 256) {
        int r = i >> 5, c = i & 31;
        sH[r * 33 + c] = g_buf2[(n0 + r) * HD + c];
    }
    __syncthreads();

    // ---- layer 1 (policy): sP = relu(h @ pW1 + pb1)
    {
        const int j0 = t, j1 = t + 256;
        float w0[32], w1[32];
#pragma unroll
        for (int k = 0; k < 32; k++) {
            w0[k] = __ldg(&pW1[k * PD + j0]);
            w1[k] = __ldg(&pW1[k * PD + j1]);
        }
        float bb0 = pb1[j0], bb1 = pb1[j1];
#pragma unroll 2
        for (int r = 0; r < 16; r++) {
            float s0 = bb0, s1 = bb1;
#pragma unroll
            for (int k = 0; k < 32; k++) {
                float hv = sH[r * 33 + k];
                s0 += hv * w0[k];
                s1 += hv * w1[k];
            }
            sP[r * 513 + j0] = fmaxf(s0, 0.f);
            sP[r * 513 + j1] = fmaxf(s1, 0.f);
        }
    }
    __syncthreads();

    // ---- layer 2 (policy): out = sP @ pW2 + pb2
    {
        int c = t & 31, rg = t >> 5;  // rows rg*2, rg*2+1
        float a0[2], a1[2];
        float bb0 = pb2[c], bb1 = pb2[c + 32];
#pragma unroll
        for (int i = 0; i < 2; i++) { a0[i] = bb0; a1[i] = bb1; }
#pragma unroll 4
        for (int k = 0; k < PD; k++) {
            float w0 = __ldg(&pW2[k * AD + c]);
            float w1 = __ldg(&pW2[k * AD + 32 + c]);
#pragma unroll
            for (int i = 0; i < 2; i++) {
                float p = sP[(rg * 2 + i) * 513 + k];
                a0[i] += p * w0;
                a1[i] += p * w1;
            }
        }
#pragma unroll
        for (int i = 0; i < 2; i++) {
            long long r = n0 + rg * 2 + i;
            out[r * AD + c] = a0[i];
            out[r * AD + 32 + c] = a1[i];
        }
    }
    __syncthreads();

    // ---- layer 1 (value): sP = relu(h @ vW1 + vb1)
    {
        const int j0 = t, j1 = t + 256;
        float w0[32], w1[32];
#pragma unroll
        for (int k = 0; k < 32; k++) {
            w0[k] = __ldg(&vW1[k * PD + j0]);
            w1[k] = __ldg(&vW1[k * PD + j1]);
        }
        float bb0 = vb1[j0], bb1 = vb1[j1];
#pragma unroll 2
        for (int r = 0; r < 16; r++) {
            float s0 = bb0, s1 = bb1;
#pragma unroll
            for (int k = 0; k < 32; k++) {
                float hv = sH[r * 33 + k];
                s0 += hv * w0[k];
                s1 += hv * w1[k];
            }
            sP[r * 513 + j0] = fmaxf(s0, 0.f);
            sP[r * 513 + j1] = fmaxf(s1, 0.f);
        }
    }
    __syncthreads();

    // ---- layer 2 (value): one thread per row; stride-513 -> conflict-free
    if (t < 16) {
        float s = vb2[0];
        for (int k = 0; k < PD; k++) s += sP[t * 513 + k] * __ldg(&vW2[k]);
        out[(long long)NN * AD + n0 + t] = s;
    }
}

// ---------------------------------------------------------------------------
// Host side: kernel launches ONLY.
// ---------------------------------------------------------------------------
extern "C" void kernel_launch(void* const* d_in, const int* in_sizes, int n_in,
                              void* d_out, int out_size) {
    const float* feat = (const float*)d_in[0];
    const int* ei = (const int*)d_in[1];  // int32! (JAX x64-off demotes int64)
    const float* W1 = (const float*)d_in[2];
    const float* b1 = (const float*)d_in[3];
    const float* W2 = (const float*)d_in[4];
    const float* b2 = (const float*)d_in[5];
    const float* pW1 = (const float*)d_in[6];
    const float* pb1 = (const float*)d_in[7];
    const float* pW2 = (const float*)d_in[8];
    const float* pb2 = (const float*)d_in[9];
    const float* vW1 = (const float*)d_in[10];
    const float* vb1 = (const float*)d_in[11];
    const float* vW2 = (const float*)d_in[12];
    const float* vb2 = (const float*)d_in[13];
    float* out = (float*)d_out;

    const int* src = ei;       // edge_index[0]
    const int* dst = ei + NE;  // edge_index[1]

    const int EB = (int)(((long long)NE * 32 + 255) / 256);

    k_zerodeg<<<(NN + 255) / 256, 256>>>();
    k_deg<<<(NE + 255) / 256, 256>>>(dst);
    k_dinv<<<(NN + 255) / 256, 256>>>();

    // conv1: buf1 = feat@W1 ; buf2 = aggregate ; buf1 = relu(buf2 + b1)
    k_gemm1<<<NN / 32, 256>>>(feat, W1);
    k_selfinit<0><<<(NN * HD + 255) / 256, 256>>>();
    k_edge<0><<<EB, 256>>>(src, dst);
    k_biasrelu<0><<<(NN * HD + 255) / 256, 256>>>(b1);

    // conv2: buf2 = buf1@W2 ; buf1 = aggregate ; buf2 = relu(buf1 + b2)
    k_gemm2<<<(NN + 63) / 64, 256>>>(W2);
    k_selfinit<1><<<(NN * HD + 255) / 256, 256>>>();
    k_edge<1><<<EB, 256>>>(src, dst);
    k_biasrelu<1><<<(NN * HD + 255) / 256, 256>>>(b2);

    // fused policy + value heads (reads g_buf2)
    k_head<<<NN / 16, 256>>>(pW1, pb1, pW2, pb2, vW1, vb1, vW2, vb2, out);
}

// round 8
// speedup vs baseline: 1.2188x; 1.2188x over previous
#include <cuda_runtime.h>

#define NN 100000
#define NE 1600000
#define FI 256
#define HD 32
#define AD 64
#define PD 512

// Scratch: __device__ globals referenced DIRECTLY by kernels.
__device__ float g_buf1[NN * HD];
__device__ float g_buf2[NN * HD];
__device__ float g_deg[NN];
__device__ float g_dinv[NN];

// ---------------------------------------------------------------------------
__global__ void k_zerodeg() {
    int i = blockIdx.x * blockDim.x + threadIdx.x;
    if (i < NN) g_deg[i] = 0.0f;
}

// edge_index is int32 (JAX demotes int64 -> int32 without x64 mode).
__global__ void k_deg(const int* __restrict__ dst) {
    int i = blockIdx.x * blockDim.x + threadIdx.x;
    if (i < NE) atomicAdd(&g_deg[dst[i]], 1.0f);
}

__global__ void k_dinv() {
    int i = blockIdx.x * blockDim.x + threadIdx.x;
    if (i < NN) g_dinv[i] = rsqrtf(g_deg[i] + 1.0f);  // +1 = self loop
}

// ---------------------------------------------------------------------------
// GEMM1: buf1 = features @ W1   ([100k,256] x [256,32])
// Fused epilogue: buf2 = buf1 * dinv[row]^2   (conv1 self-loop init)
// W1 (32KB) + 32x68 feature chunk (8.7KB) in static smem. Coalesced chunk
// loads; compute reads are LDS broadcasts (free) -> FMA-bound.
// ---------------------------------------------------------------------------
__global__ void __launch_bounds__(256) k_gemm1(const float* __restrict__ feat,
                                               const float* __restrict__ W1) {
    __shared__ float sW[FI * HD];   // 8192 floats = 32KB
    __shared__ float sF[32 * 68];   // 8.7KB (pad 68 vs 64)
    int t = threadIdx.x;
#pragma unroll
    for (int i = 0; i < FI * HD / 256; i++) sW[t + i * 256] = W1[t + i * 256];

    long long row0 = (long long)blockIdx.x * 32;
    int c = t & 31, rg = t >> 5;
    float a0 = 0.f, a1 = 0.f, a2 = 0.f, a3 = 0.f;

#pragma unroll
    for (int ch = 0; ch < 4; ch++) {
        __syncthreads();
        // coalesced load of 32 rows x 64 cols chunk
#pragma unroll
        for (int u = 0; u < 2; u++) {
            int f = t + u * 256;           // float4 index 0..511
            int r = f >> 4, c4 = (f & 15) * 4;
            float4 v = __ldg((const float4*)(feat + (row0 + r) * FI + ch * 64 + c4));
            *(float4*)&sF[r * 68 + c4] = v;
        }
        __syncthreads();
#pragma unroll 4
        for (int k = 0; k < 64; k += 4) {
            float4 fa = *(const float4*)&sF[rg * 68 + k];
            float4 fb = *(const float4*)&sF[(rg + 8) * 68 + k];
            float4 fc = *(const float4*)&sF[(rg + 16) * 68 + k];
            float4 fd = *(const float4*)&sF[(rg + 24) * 68 + k];
            int kg = ch * 64 + k;
            float w0 = sW[(kg + 0) * HD + c];
            float w1 = sW[(kg + 1) * HD + c];
            float w2 = sW[(kg + 2) * HD + c];
            float w3 = sW[(kg + 3) * HD + c];
            a0 += fa.x * w0 + fa.y * w1 + fa.z * w2 + fa.w * w3;
            a1 += fb.x * w0 + fb.y * w1 + fb.z * w2 + fb.w * w3;
            a2 += fc.x * w0 + fc.y * w1 + fc.z * w2 + fc.w * w3;
            a3 += fd.x * w0 + fd.y * w1 + fd.z * w2 + fd.w * w3;
        }
    }
    // epilogue: buf1 = x1, buf2 = x1 * dinv^2 (self loop)
    float d0 = g_dinv[row0 + rg], d1 = g_dinv[row0 + rg + 8];
    float d2 = g_dinv[row0 + rg + 16], d3 = g_dinv[row0 + rg + 24];
    float* o1 = g_buf1 + row0 * HD;
    float* o2 = g_buf2 + row0 * HD;
    o1[(rg) * HD + c] = a0;
    o1[(rg + 8) * HD + c] = a1;
    o1[(rg + 16) * HD + c] = a2;
    o1[(rg + 24) * HD + c] = a3;
    o2[(rg) * HD + c] = a0 * d0 * d0;
    o2[(rg + 8) * HD + c] = a1 * d1 * d1;
    o2[(rg + 16) * HD + c] = a2 * d2 * d2;
    o2[(rg + 24) * HD + c] = a3 * d3 * d3;
}

// ---------------------------------------------------------------------------
// Edge scatter: 8 lanes per edge, each lane does ONE red.global.add.v4.f32
// (4x fewer L2 atomic ops than scalar atomicAdd).
// agg[dst][q*4..q*4+3] += x[src][q*4..q*4+3] * dinv[src]*dinv[dst]
// ---------------------------------------------------------------------------
template <int DIR>
__global__ void k_edge(const int* __restrict__ src, const int* __restrict__ dst) {
    const float* x = DIR ? g_buf2 : g_buf1;
    float* agg = DIR ? g_buf1 : g_buf2;
    int gt = blockIdx.x * blockDim.x + threadIdx.x;
    int e = gt >> 3;
    if (e >= NE) return;
    int q = threadIdx.x & 7;
    int s = src[e];
    int d = dst[e];
    float nrm = g_dinv[s] * g_dinv[d];
    float4 xv = __ldg((const float4*)(x + (long long)s * HD + q * 4));
    float* p = agg + (long long)d * HD + q * 4;
    asm volatile("red.global.add.v4.f32 [%0], {%1, %2, %3, %4};"
                 :: "l"(p), "f"(xv.x * nrm), "f"(xv.y * nrm),
                    "f"(xv.z * nrm), "f"(xv.w * nrm)
                 : "memory");
}

// ---------------------------------------------------------------------------
// GEMM2: x2 = relu(agg1 + b1) @ W2  ([100k,32] x [32,32])
// reads buf2 (conv1 aggregate), writes buf2 = x2 (own rows only -> safe)
// and buf1 = x2 * dinv^2 (conv2 self-loop init). 64 rows per block.
// ---------------------------------------------------------------------------
__global__ void __launch_bounds__(256) k_gemm2(const float* __restrict__ W2,
                                               const float* __restrict__ b1) {
    __shared__ float sW[HD * HD];   // 4KB
    __shared__ float sH[64 * 33];   // 8.25KB
    int t = threadIdx.x;
    for (int i = t; i < HD * HD; i += 256) sW[i] = W2[i];
    int row0 = blockIdx.x * 64;
    for (int i = t; i < 64 * 32; i += 256) {
        int r = i >> 5, c = i & 31;
        int gr = row0 + r;
        sH[r * 33 + c] = (gr < NN) ? fmaxf(g_buf2[(long long)gr * HD + c] + b1[c], 0.f) : 0.f;
    }
    __syncthreads();
    int c = t & 31, rg = t >> 5;
    float acc[8];
#pragma unroll
    for (int i = 0; i < 8; i++) acc[i] = 0.f;
#pragma unroll
    for (int k = 0; k < HD; k++) {
        float w = sW[k * HD + c];
#pragma unroll
        for (int i = 0; i < 8; i++) acc[i] += sH[(rg + 8 * i) * 33 + k] * w;
    }
#pragma unroll
    for (int i = 0; i < 8; i++) {
        int gr = row0 + rg + 8 * i;
        if (gr < NN) {
            float dv = g_dinv[gr];
            g_buf2[(long long)gr * HD + c] = acc[i];
            g_buf1[(long long)gr * HD + c] = acc[i] * dv * dv;
        }
    }
}

// ---------------------------------------------------------------------------
// Fused heads, 16-node tile (static smem 41.3KB). Input h2 = relu(buf1 + b2)
// computed on load (bias+relu folded in).
// ---------------------------------------------------------------------------
__global__ void __launch_bounds__(256) k_head(
    const float* __restrict__ b2,
    const float* __restrict__ pW1, const float* __restrict__ pb1,
    const float* __restrict__ pW2, const float* __restrict__ pb2,
    const float* __restrict__ vW1, const float* __restrict__ vb1,
    const float* __restrict__ vW2, const float* __restrict__ vb2,
    float* __restrict__ out) {
    __shared__ float sH[16 * 33];   // 2112 floats
    __shared__ float sP[16 * 513];  // 8208 floats
    const int t = threadIdx.x;
    const int n0 = blockIdx.x * 16;

    for (int i = t; i < 16 * 32; i += 256) {
        int r = i >> 5, c = i & 31;
        sH[r * 33 + c] = fmaxf(g_buf1[(long long)(n0 + r) * HD + c] + b2[c], 0.f);
    }
    __syncthreads();

    // ---- layer 1 (policy): sP = relu(h @ pW1 + pb1)
    {
        const int j0 = t, j1 = t + 256;
        float w0[32], w1[32];
#pragma unroll
        for (int k = 0; k < 32; k++) {
            w0[k] = __ldg(&pW1[k * PD + j0]);
            w1[k] = __ldg(&pW1[k * PD + j1]);
        }
        float bb0 = pb1[j0], bb1 = pb1[j1];
#pragma unroll 2
        for (int r = 0; r < 16; r++) {
            float s0 = bb0, s1 = bb1;
#pragma unroll
            for (int k = 0; k < 32; k++) {
                float hv = sH[r * 33 + k];
                s0 += hv * w0[k];
                s1 += hv * w1[k];
            }
            sP[r * 513 + j0] = fmaxf(s0, 0.f);
            sP[r * 513 + j1] = fmaxf(s1, 0.f);
        }
    }
    __syncthreads();

    // ---- layer 2 (policy): out = sP @ pW2 + pb2
    {
        int c = t & 31, rg = t >> 5;  // rows rg*2, rg*2+1
        float a0[2], a1[2];
        float bb0 = pb2[c], bb1 = pb2[c + 32];
#pragma unroll
        for (int i = 0; i < 2; i++) { a0[i] = bb0; a1[i] = bb1; }
#pragma unroll 4
        for (int k = 0; k < PD; k++) {
            float w0 = __ldg(&pW2[k * AD + c]);
            float w1 = __ldg(&pW2[k * AD + 32 + c]);
#pragma unroll
            for (int i = 0; i < 2; i++) {
                float p = sP[(rg * 2 + i) * 513 + k];
                a0[i] += p * w0;
                a1[i] += p * w1;
            }
        }
#pragma unroll
        for (int i = 0; i < 2; i++) {
            long long r = n0 + rg * 2 + i;
            out[r * AD + c] = a0[i];
            out[r * AD + 32 + c] = a1[i];
        }
    }
    __syncthreads();

    // ---- layer 1 (value): sP = relu(h @ vW1 + vb1)
    {
        const int j0 = t, j1 = t + 256;
        float w0[32], w1[32];
#pragma unroll
        for (int k = 0; k < 32; k++) {
            w0[k] = __ldg(&vW1[k * PD + j0]);
            w1[k] = __ldg(&vW1[k * PD + j1]);
        }
        float bb0 = vb1[j0], bb1 = vb1[j1];
#pragma unroll 2
        for (int r = 0; r < 16; r++) {
            float s0 = bb0, s1 = bb1;
#pragma unroll
            for (int k = 0; k < 32; k++) {
                float hv = sH[r * 33 + k];
                s0 += hv * w0[k];
                s1 += hv * w1[k];
            }
            sP[r * 513 + j0] = fmaxf(s0, 0.f);
            sP[r * 513 + j1] = fmaxf(s1, 0.f);
        }
    }
    __syncthreads();

    // ---- layer 2 (value): one thread per row; stride-513 -> conflict-free
    if (t < 16) {
        float s = vb2[0];
        for (int k = 0; k < PD; k++) s += sP[t * 513 + k] * __ldg(&vW2[k]);
        out[(long long)NN * AD + n0 + t] = s;
    }
}

// ---------------------------------------------------------------------------
// Host side: kernel launches ONLY.
// ---------------------------------------------------------------------------
extern "C" void kernel_launch(void* const* d_in, const int* in_sizes, int n_in,
                              void* d_out, int out_size) {
    const float* feat = (const float*)d_in[0];
    const int* ei = (const int*)d_in[1];  // int32 (JAX x64-off)
    const float* W1 = (const float*)d_in[2];
    const float* b1 = (const float*)d_in[3];
    const float* W2 = (const float*)d_in[4];
    const float* b2 = (const float*)d_in[5];
    const float* pW1 = (const float*)d_in[6];
    const float* pb1 = (const float*)d_in[7];
    const float* pW2 = (const float*)d_in[8];
    const float* pb2 = (const float*)d_in[9];
    const float* vW1 = (const float*)d_in[10];
    const float* vb1 = (const float*)d_in[11];
    const float* vW2 = (const float*)d_in[12];
    const float* vb2 = (const float*)d_in[13];
    float* out = (float*)d_out;

    const int* src = ei;       // edge_index[0]
    const int* dst = ei + NE;  // edge_index[1]

    const int EB8 = (int)(((long long)NE * 8 + 255) / 256);

    k_zerodeg<<<(NN + 255) / 256, 256>>>();
    k_deg<<<(NE + 255) / 256, 256>>>(dst);
    k_dinv<<<(NN + 255) / 256, 256>>>();

    // conv1: buf1 = x1 = feat@W1, buf2 = x1*dinv^2 ; buf2 += edges
    k_gemm1<<<NN / 32, 256>>>(feat, W1);
    k_edge<0><<<EB8, 256>>>(src, dst);

    // conv2: buf2 = x2 = relu(buf2+b1)@W2, buf1 = x2*dinv^2 ; buf1 += edges
    k_gemm2<<<(NN + 63) / 64, 256>>>(W2, b1);
    k_edge<1><<<EB8, 256>>>(src, dst);

    // heads: read relu(buf1 + b2)
    k_head<<<NN / 16, 256>>>(b2, pW1, pb1, pW2, pb2, vW1, vb1, vW2, vb2, out);
}

// round 9
// speedup vs baseline: 1.6774x; 1.3763x over previous
#include <cuda_runtime.h>

#define NN 100000
#define NE 1600000
#define FI 256
#define HD 32
#define AD 64
#define PD 512

// Scratch: __device__ globals referenced DIRECTLY by kernels.
__device__ float g_buf1[NN * HD];
__device__ float g_buf2[NN * HD];
__device__ float g_deg[NN];
__device__ float g_dinv[NN];

// ---- packed f32x2 helpers (FFMA2: 2 fp32 MACs per issue; PTX-only) -------
__device__ __forceinline__ unsigned long long pk2(float lo, float hi) {
    unsigned long long r;
    asm("mov.b64 %0, {%1, %2};" : "=l"(r) : "f"(lo), "f"(hi));
    return r;
}
__device__ __forceinline__ void fma2(unsigned long long& d, unsigned long long a,
                                     unsigned long long b) {
    asm("fma.rn.f32x2 %0, %1, %2, %0;" : "+l"(d) : "l"(a), "l"(b));
}
__device__ __forceinline__ float lohi(unsigned long long v) {
    float lo, hi;
    asm("mov.b64 {%0, %1}, %2;" : "=f"(lo), "=f"(hi) : "l"(v));
    return lo + hi;
}

// ---------------------------------------------------------------------------
__global__ void k_zerodeg() {
    int i = blockIdx.x * blockDim.x + threadIdx.x;
    if (i < NN) g_deg[i] = 0.0f;
}

// edge_index is int32 (JAX demotes int64 -> int32 without x64 mode).
__global__ void k_deg(const int* __restrict__ dst) {
    int i = blockIdx.x * blockDim.x + threadIdx.x;
    if (i < NE) atomicAdd(&g_deg[dst[i]], 1.0f);
}

__global__ void k_dinv() {
    int i = blockIdx.x * blockDim.x + threadIdx.x;
    if (i < NN) g_dinv[i] = rsqrtf(g_deg[i] + 1.0f);  // +1 = self loop
}

// ---------------------------------------------------------------------------
// GEMM1: buf1 = features @ W1 ; buf2 = buf1 * dinv^2 (conv1 self-loop init)
// Double-buffered 32-col feature chunks: LDG for chunk ch+1 held in registers
// while computing chunk ch -> DRAM latency hidden behind FFMAs.
// ---------------------------------------------------------------------------
__global__ void __launch_bounds__(256) k_gemm1(const float* __restrict__ feat,
                                               const float* __restrict__ W1) {
    __shared__ float sW[FI * HD];      // 32KB
    __shared__ float sF[2][32 * 36];   // 9KB double buffer (stride 36 for 16B align)
    int t = threadIdx.x;
#pragma unroll
    for (int i = 0; i < FI * HD / 256; i++) sW[t + i * 256] = W1[t + i * 256];

    long long row0 = (long long)blockIdx.x * 32;
    int lr = t >> 3, c4 = (t & 7) * 4;  // loader coords: 1 float4/thread/chunk
    const float* fp = feat + (row0 + lr) * FI + c4;

    // prime chunk 0
    {
        float4 v = __ldg((const float4*)fp);
        *(float4*)&sF[0][lr * 36 + c4] = v;
    }
    __syncthreads();

    int c = t & 31, rg = t >> 5;
    float a0 = 0.f, a1 = 0.f, a2 = 0.f, a3 = 0.f;

#pragma unroll
    for (int ch = 0; ch < 8; ch++) {
        float4 nv;
        if (ch < 7) nv = __ldg((const float4*)(fp + (ch + 1) * 32));
        const float* sf = sF[ch & 1];
#pragma unroll
        for (int k = 0; k < 32; k += 4) {
            float4 fa = *(const float4*)&sf[rg * 36 + k];
            float4 fb = *(const float4*)&sf[(rg + 8) * 36 + k];
            float4 fc = *(const float4*)&sf[(rg + 16) * 36 + k];
            float4 fd = *(const float4*)&sf[(rg + 24) * 36 + k];
            int kg = ch * 32 + k;
            float w0 = sW[(kg + 0) * HD + c];
            float w1 = sW[(kg + 1) * HD + c];
            float w2 = sW[(kg + 2) * HD + c];
            float w3 = sW[(kg + 3) * HD + c];
            a0 += fa.x * w0 + fa.y * w1 + fa.z * w2 + fa.w * w3;
            a1 += fb.x * w0 + fb.y * w1 + fb.z * w2 + fb.w * w3;
            a2 += fc.x * w0 + fc.y * w1 + fc.z * w2 + fc.w * w3;
            a3 += fd.x * w0 + fd.y * w1 + fd.z * w2 + fd.w * w3;
        }
        __syncthreads();
        if (ch < 7) {
            *(float4*)&sF[(ch + 1) & 1][lr * 36 + c4] = nv;
            __syncthreads();
        }
    }

    float d0 = g_dinv[row0 + rg], d1 = g_dinv[row0 + rg + 8];
    float d2 = g_dinv[row0 + rg + 16], d3 = g_dinv[row0 + rg + 24];
    float* o1 = g_buf1 + row0 * HD;
    float* o2 = g_buf2 + row0 * HD;
    o1[(rg) * HD + c] = a0;
    o1[(rg + 8) * HD + c] = a1;
    o1[(rg + 16) * HD + c] = a2;
    o1[(rg + 24) * HD + c] = a3;
    o2[(rg) * HD + c] = a0 * d0 * d0;
    o2[(rg + 8) * HD + c] = a1 * d1 * d1;
    o2[(rg + 16) * HD + c] = a2 * d2 * d2;
    o2[(rg + 24) * HD + c] = a3 * d3 * d3;
}

// ---------------------------------------------------------------------------
// Edge scatter: 8 lanes per edge, one red.global.add.v4.f32 per lane.
// ---------------------------------------------------------------------------
template <int DIR>
__global__ void k_edge(const int* __restrict__ src, const int* __restrict__ dst) {
    const float* x = DIR ? g_buf2 : g_buf1;
    float* agg = DIR ? g_buf1 : g_buf2;
    int gt = blockIdx.x * blockDim.x + threadIdx.x;
    int e = gt >> 3;
    if (e >= NE) return;
    int q = threadIdx.x & 7;
    int s = src[e];
    int d = dst[e];
    float nrm = g_dinv[s] * g_dinv[d];
    float4 xv = __ldg((const float4*)(x + (long long)s * HD + q * 4));
    float* p = agg + (long long)d * HD + q * 4;
    asm volatile("red.global.add.v4.f32 [%0], {%1, %2, %3, %4};"
                 :: "l"(p), "f"(xv.x * nrm), "f"(xv.y * nrm),
                    "f"(xv.z * nrm), "f"(xv.w * nrm)
                 : "memory");
}

// ---------------------------------------------------------------------------
// GEMM2: x2 = relu(agg1 + b1) @ W2 ; buf2 = x2 ; buf1 = x2 * dinv^2
// ---------------------------------------------------------------------------
__global__ void __launch_bounds__(256) k_gemm2(const float* __restrict__ W2,
                                               const float* __restrict__ b1) {
    __shared__ float sW[HD * HD];
    __shared__ float sH[64 * 33];
    int t = threadIdx.x;
    for (int i = t; i < HD * HD; i += 256) sW[i] = W2[i];
    int row0 = blockIdx.x * 64;
    for (int i = t; i < 64 * 32; i += 256) {
        int r = i >> 5, c = i & 31;
        int gr = row0 + r;
        sH[r * 33 + c] = (gr < NN) ? fmaxf(g_buf2[(long long)gr * HD + c] + b1[c], 0.f) : 0.f;
    }
    __syncthreads();
    int c = t & 31, rg = t >> 5;
    float acc[8];
#pragma unroll
    for (int i = 0; i < 8; i++) acc[i] = 0.f;
#pragma unroll
    for (int k = 0; k < HD; k++) {
        float w = sW[k * HD + c];
#pragma unroll
        for (int i = 0; i < 8; i++) acc[i] += sH[(rg + 8 * i) * 33 + k] * w;
    }
#pragma unroll
    for (int i = 0; i < 8; i++) {
        int gr = row0 + rg + 8 * i;
        if (gr < NN) {
            float dv = g_dinv[gr];
            g_buf2[(long long)gr * HD + c] = acc[i];
            g_buf1[(long long)gr * HD + c] = acc[i] * dv * dv;
        }
    }
}

// ---------------------------------------------------------------------------
// Head layer 1 (shared policy/value): sP = relu(sH @ W + b), f32x2 packed.
// Each thread: 2 output cols (t, t+256), k packed in pairs.
// ---------------------------------------------------------------------------
__device__ __forceinline__ void mlp_layer1(const float* __restrict__ W,
                                           const float* __restrict__ b,
                                           const float* sH, float* sP, int t) {
    const int j0 = t, j1 = t + 256;
    unsigned long long w0p[16], w1p[16];
#pragma unroll
    for (int k2 = 0; k2 < 16; k2++) {
        w0p[k2] = pk2(__ldg(&W[(2 * k2) * PD + j0]), __ldg(&W[(2 * k2 + 1) * PD + j0]));
        w1p[k2] = pk2(__ldg(&W[(2 * k2) * PD + j1]), __ldg(&W[(2 * k2 + 1) * PD + j1]));
    }
    float bb0 = b[j0], bb1 = b[j1];
#pragma unroll 2
    for (int r = 0; r < 16; r++) {
        unsigned long long s0 = pk2(bb0, 0.f), s1 = pk2(bb1, 0.f);
#pragma unroll
        for (int k2 = 0; k2 < 16; k2++) {
            unsigned long long hp = *(const unsigned long long*)&sH[r * 34 + 2 * k2];
            fma2(s0, hp, w0p[k2]);
            fma2(s1, hp, w1p[k2]);
        }
        sP[r * 514 + j0] = fmaxf(lohi(s0), 0.f);
        sP[r * 514 + j1] = fmaxf(lohi(s1), 0.f);
    }
}

// ---------------------------------------------------------------------------
// Fused heads, 16-node tile. Input h2 = relu(buf1 + b2) computed on load.
// sH stride 34 / sP stride 514: even strides keep f32x2 8B loads aligned.
// ---------------------------------------------------------------------------
__global__ void __launch_bounds__(256) k_head(
    const float* __restrict__ b2,
    const float* __restrict__ pW1, const float* __restrict__ pb1,
    const float* __restrict__ pW2, const float* __restrict__ pb2,
    const float* __restrict__ vW1, const float* __restrict__ vb1,
    const float* __restrict__ vW2, const float* __restrict__ vb2,
    float* __restrict__ out) {
    __shared__ float sH[16 * 34];   // 2.1KB
    __shared__ float sP[16 * 514];  // 32.9KB
    const int t = threadIdx.x;
    const int n0 = blockIdx.x * 16;

    for (int i = t; i < 16 * 32; i += 256) {
        int r = i >> 5, c = i & 31;
        sH[r * 34 + c] = fmaxf(g_buf1[(long long)(n0 + r) * HD + c] + b2[c], 0.f);
    }
    __syncthreads();

    // ---- policy layer 1
    mlp_layer1(pW1, pb1, sH, sP, t);
    __syncthreads();

    // ---- policy layer 2: out = sP @ pW2 + pb2 (f32x2 packed over k)
    {
        int c = t & 31, rg = t >> 5;  // rows rg*2, rg*2+1
        unsigned long long a0[2], a1[2];
        a0[0] = a0[1] = pk2(pb2[c], 0.f);
        a1[0] = a1[1] = pk2(pb2[c + 32], 0.f);
#pragma unroll 4
        for (int k = 0; k < PD; k += 2) {
            unsigned long long w0 =
                pk2(__ldg(&pW2[k * AD + c]), __ldg(&pW2[(k + 1) * AD + c]));
            unsigned long long w1 =
                pk2(__ldg(&pW2[k * AD + 32 + c]), __ldg(&pW2[(k + 1) * AD + 32 + c]));
#pragma unroll
            for (int i = 0; i < 2; i++) {
                unsigned long long p =
                    *(const unsigned long long*)&sP[(rg * 2 + i) * 514 + k];
                fma2(a0[i], p, w0);
                fma2(a1[i], p, w1);
            }
        }
#pragma unroll
        for (int i = 0; i < 2; i++) {
            long long r = n0 + rg * 2 + i;
            out[r * AD + c] = lohi(a0[i]);
            out[r * AD + 32 + c] = lohi(a1[i]);
        }
    }
    __syncthreads();

    // ---- value layer 1
    mlp_layer1(vW1, vb1, sH, sP, t);
    __syncthreads();

    // ---- value layer 2: 8 warps x 2 rows, 16-lane strided dot + shuffle reduce
    {
        int wid = t >> 5, l = t & 31;
        int row = wid * 2 + (l >> 4);
        int k0 = l & 15;
        float s = 0.f;
#pragma unroll
        for (int k = k0; k < PD; k += 16) s += sP[row * 514 + k] * __ldg(&vW2[k]);
        s += __shfl_down_sync(0xffffffffu, s, 8);
        s += __shfl_down_sync(0xffffffffu, s, 4);
        s += __shfl_down_sync(0xffffffffu, s, 2);
        s += __shfl_down_sync(0xffffffffu, s, 1);
        if (k0 == 0) out[(long long)NN * AD + n0 + row] = s + vb2[0];
    }
}

// ---------------------------------------------------------------------------
// Host side: kernel launches ONLY.
// ---------------------------------------------------------------------------
extern "C" void kernel_launch(void* const* d_in, const int* in_sizes, int n_in,
                              void* d_out, int out_size) {
    const float* feat = (const float*)d_in[0];
    const int* ei = (const int*)d_in[1];  // int32 (JAX x64-off)
    const float* W1 = (const float*)d_in[2];
    const float* b1 = (const float*)d_in[3];
    const float* W2 = (const float*)d_in[4];
    const float* b2 = (const float*)d_in[5];
    const float* pW1 = (const float*)d_in[6];
    const float* pb1 = (const float*)d_in[7];
    const float* pW2 = (const float*)d_in[8];
    const float* pb2 = (const float*)d_in[9];
    const float* vW1 = (const float*)d_in[10];
    const float* vb1 = (const float*)d_in[11];
    const float* vW2 = (const float*)d_in[12];
    const float* vb2 = (const float*)d_in[13];
    float* out = (float*)d_out;

    const int* src = ei;       // edge_index[0]
    const int* dst = ei + NE;  // edge_index[1]

    const int EB8 = (int)(((long long)NE * 8 + 255) / 256);

    k_zerodeg<<<(NN + 255) / 256, 256>>>();
    k_deg<<<(NE + 255) / 256, 256>>>(dst);
    k_dinv<<<(NN + 255) / 256, 256>>>();

    // conv1: buf1 = x1 = feat@W1, buf2 = x1*dinv^2 ; buf2 += edges
    k_gemm1<<<NN / 32, 256>>>(feat, W1);
    k_edge<0><<<EB8, 256>>>(src, dst);

    // conv2: buf2 = x2 = relu(buf2+b1)@W2, buf1 = x2*dinv^2 ; buf1 += edges
    k_gemm2<<<(NN + 63) / 64, 256>>>(W2, b1);
    k_edge<1><<<EB8, 256>>>(src, dst);

    // heads: read relu(buf1 + b2)
    k_head<<<NN / 16, 256>>>(b2, pW1, pb1, pW2, pb2, vW1, vb1, vW2, vb2, out);
}

// round 10
// speedup vs baseline: 2.0765x; 1.2379x over previous
#include <cuda_runtime.h>

#define NN 100000
#define NE 1600000
#define FI 256
#define HD 32
#define AD 64
#define PD 512

// Scratch (device globals; no allocation allowed)
__device__ float g_buf1[NN * HD];
__device__ float g_buf2[NN * HD];
__device__ float g_dinv[NN];
__device__ int g_degi[NN];
__device__ int g_off[NN];
__device__ int g_cur[NN];
__device__ int g_csr[NE];
__device__ int g_bsum[128];
__device__ int g_boff[128];

#define NB_SCAN 98  // ceil(100000/1024)

// ---- packed f32x2 helpers (FFMA2: 2 fp32 MACs per issue; PTX-only) -------
__device__ __forceinline__ unsigned long long pk2(float lo, float hi) {
    unsigned long long r;
    asm("mov.b64 %0, {%1, %2};" : "=l"(r) : "f"(lo), "f"(hi));
    return r;
}
__device__ __forceinline__ void fma2(unsigned long long& d, unsigned long long a,
                                     unsigned long long b) {
    asm("fma.rn.f32x2 %0, %1, %2, %0;" : "+l"(d) : "l"(a), "l"(b));
}
__device__ __forceinline__ float lohi(unsigned long long v) {
    float lo, hi;
    asm("mov.b64 {%0, %1}, %2;" : "=f"(lo), "=f"(hi) : "l"(v));
    return lo + hi;
}

// ============================ CSR construction =============================
__global__ void k_zero() {
    int i = blockIdx.x * blockDim.x + threadIdx.x;
    if (i < NN) g_degi[i] = 0;
}

__global__ void k_hist(const int* __restrict__ dst) {
    int i = blockIdx.x * blockDim.x + threadIdx.x;
    if (i < NE) atomicAdd(&g_degi[dst[i]], 1);
}

// per-1024-chunk sums
__global__ void k_bsum() {
    __shared__ int sh[256];
    int b = blockIdx.x, t = threadIdx.x;
    int s = 0;
#pragma unroll
    for (int j = 0; j < 4; j++) {
        int i = b * 1024 + t + j * 256;
        if (i < NN) s += g_degi[i];
    }
    sh[t] = s;
    __syncthreads();
    for (int o = 128; o > 0; o >>= 1) {
        if (t < o) sh[t] += sh[t + o];
        __syncthreads();
    }
    if (t == 0) g_bsum[b] = sh[0];
}

// exclusive scan of the 98 chunk sums (single block, Hillis-Steele)
__global__ void k_scanb() {
    __shared__ int sh[128];
    int t = threadIdx.x;
    int v = (t < NB_SCAN) ? g_bsum[t] : 0;
    sh[t] = v;
    __syncthreads();
#pragma unroll
    for (int o = 1; o < 128; o <<= 1) {
        int x = (t >= o) ? sh[t - o] : 0;
        __syncthreads();
        sh[t] += x;
        __syncthreads();
    }
    if (t < NB_SCAN) g_boff[t] = sh[t] - v;
}

// per-chunk exclusive scan + add chunk base -> offsets & cursors
__global__ void k_off() {
    __shared__ int sh[1024];
    int b = blockIdx.x, t = threadIdx.x;
    int i = b * 1024 + t;
    int v = (i < NN) ? g_degi[i] : 0;
    sh[t] = v;
    __syncthreads();
#pragma unroll
    for (int o = 1; o < 1024; o <<= 1) {
        int x = (t >= o) ? sh[t - o] : 0;
        __syncthreads();
        sh[t] += x;
        __syncthreads();
    }
    if (i < NN) {
        int off = g_boff[b] + sh[t] - v;
        g_off[i] = off;
        g_cur[i] = off;
    }
}

__global__ void k_dinv() {
    int i = blockIdx.x * blockDim.x + threadIdx.x;
    if (i < NN) g_dinv[i] = rsqrtf((float)g_degi[i] + 1.0f);  // +1 self loop
}

__global__ void k_fill(const int* __restrict__ src, const int* __restrict__ dst) {
    int i = blockIdx.x * blockDim.x + threadIdx.x;
    if (i < NE) {
        int pos = atomicAdd(&g_cur[dst[i]], 1);
        g_csr[pos] = src[i];
    }
}

// ---------------------------------------------------------------------------
// GEMM1: buf1 = (features @ W1) * dinv   (pre-scaled for gather: xs1)
// ---------------------------------------------------------------------------
__global__ void __launch_bounds__(256) k_gemm1(const float* __restrict__ feat,
                                               const float* __restrict__ W1) {
    __shared__ float sW[FI * HD];   // 32KB
    __shared__ float sF[32 * 68];   // 8.7KB
    int t = threadIdx.x;
#pragma unroll
    for (int i = 0; i < FI * HD / 256; i++) sW[t + i * 256] = W1[t + i * 256];

    long long row0 = (long long)blockIdx.x * 32;
    int c = t & 31, rg = t >> 5;
    float a0 = 0.f, a1 = 0.f, a2 = 0.f, a3 = 0.f;

#pragma unroll
    for (int ch = 0; ch < 4; ch++) {
        __syncthreads();
#pragma unroll
        for (int u = 0; u < 2; u++) {
            int f = t + u * 256;
            int r = f >> 4, c4 = (f & 15) * 4;
            float4 v = __ldg((const float4*)(feat + (row0 + r) * FI + ch * 64 + c4));
            *(float4*)&sF[r * 68 + c4] = v;
        }
        __syncthreads();
#pragma unroll 4
        for (int k = 0; k < 64; k += 4) {
            float4 fa = *(const float4*)&sF[rg * 68 + k];
            float4 fb = *(const float4*)&sF[(rg + 8) * 68 + k];
            float4 fc = *(const float4*)&sF[(rg + 16) * 68 + k];
            float4 fd = *(const float4*)&sF[(rg + 24) * 68 + k];
            int kg = ch * 64 + k;
            float w0 = sW[(kg + 0) * HD + c];
            float w1 = sW[(kg + 1) * HD + c];
            float w2 = sW[(kg + 2) * HD + c];
            float w3 = sW[(kg + 3) * HD + c];
            a0 += fa.x * w0 + fa.y * w1 + fa.z * w2 + fa.w * w3;
            a1 += fb.x * w0 + fb.y * w1 + fb.z * w2 + fb.w * w3;
            a2 += fc.x * w0 + fc.y * w1 + fc.z * w2 + fc.w * w3;
            a3 += fd.x * w0 + fd.y * w1 + fd.z * w2 + fd.w * w3;
        }
    }
    float d0 = g_dinv[row0 + rg], d1 = g_dinv[row0 + rg + 8];
    float d2 = g_dinv[row0 + rg + 16], d3 = g_dinv[row0 + rg + 24];
    float* o = g_buf1 + row0 * HD;
    o[(rg) * HD + c] = a0 * d0;
    o[(rg + 8) * HD + c] = a1 * d1;
    o[(rg + 16) * HD + c] = a2 * d2;
    o[(rg + 24) * HD + c] = a3 * d3;
}

// ---------------------------------------------------------------------------
// Gather aggregation (NO atomics): one warp per node, lane = feature col.
// agg[n] = dinv[n] * ( xs[n] + sum_{s in N(n)} xs[s] )
//   (xs = x*dinv, so this equals dinv[n]^2*x[n] + sum dinv_s*dinv_n*x[s])
// DIR=0: xs=buf1 -> agg=buf2.   DIR=1: xs=buf1 -> agg=buf2 (same; buffers
// are reused via the gemm stage in between).
// ---------------------------------------------------------------------------
template <int SRCBUF>
__global__ void __launch_bounds__(256) k_gather() {
    const float* xs = SRCBUF ? g_buf1 : g_buf1;  // always buf1 (xs), kept template for clarity
    float* agg = g_buf2;
    int node = blockIdx.x * 8 + (threadIdx.x >> 5);
    if (node >= NN) return;
    int c = threadIdx.x & 31;
    int off = g_off[node];
    int cnt = g_degi[node];
    float acc = xs[(long long)node * HD + c];
#pragma unroll 4
    for (int j = 0; j < cnt; j++) {
        int s = __ldg(&g_csr[off + j]);               // warp-broadcast load
        acc += __ldg(&xs[(long long)s * HD + c]);     // coalesced 128B row
    }
    agg[(long long)node * HD + c] = acc * g_dinv[node];
}

// ---------------------------------------------------------------------------
// GEMM2: x2 = relu(agg1 + b1) @ W2 ; buf1 = x2 * dinv  (xs2, for gather 2)
// reads buf2, writes buf1. 64 rows per block.
// ---------------------------------------------------------------------------
__global__ void __launch_bounds__(256) k_gemm2(const float* __restrict__ W2,
                                               const float* __restrict__ b1) {
    __shared__ float sW[HD * HD];
    __shared__ float sH[64 * 33];
    int t = threadIdx.x;
    for (int i = t; i < HD * HD; i += 256) sW[i] = W2[i];
    int row0 = blockIdx.x * 64;
    for (int i = t; i < 64 * 32; i += 256) {
        int r = i >> 5, c = i & 31;
        int gr = row0 + r;
        sH[r * 33 + c] = (gr < NN) ? fmaxf(g_buf2[(long long)gr * HD + c] + b1[c], 0.f) : 0.f;
    }
    __syncthreads();
    int c = t & 31, rg = t >> 5;
    float acc[8];
#pragma unroll
    for (int i = 0; i < 8; i++) acc[i] = 0.f;
#pragma unroll
    for (int k = 0; k < HD; k++) {
        float w = sW[k * HD + c];
#pragma unroll
        for (int i = 0; i < 8; i++) acc[i] += sH[(rg + 8 * i) * 33 + k] * w;
    }
#pragma unroll
    for (int i = 0; i < 8; i++) {
        int gr = row0 + rg + 8 * i;
        if (gr < NN) g_buf1[(long long)gr * HD + c] = acc[i] * g_dinv[gr];
    }
}

// ---------------------------------------------------------------------------
// Head layer 1 (policy/value shared): sP = relu(sH @ W + b), f32x2 packed.
// 32 rows per tile; each thread owns 2 output cols (t, t+256).
// ---------------------------------------------------------------------------
__device__ __forceinline__ void mlp_layer1(const float* __restrict__ W,
                                           const float* __restrict__ b,
                                           const float* sH, float* sP, int t) {
    const int j0 = t, j1 = t + 256;
    unsigned long long w0p[16], w1p[16];
#pragma unroll
    for (int k2 = 0; k2 < 16; k2++) {
        w0p[k2] = pk2(__ldg(&W[(2 * k2) * PD + j0]), __ldg(&W[(2 * k2 + 1) * PD + j0]));
        w1p[k2] = pk2(__ldg(&W[(2 * k2) * PD + j1]), __ldg(&W[(2 * k2 + 1) * PD + j1]));
    }
    float bb0 = b[j0], bb1 = b[j1];
#pragma unroll 2
    for (int r = 0; r < 32; r++) {
        unsigned long long s0 = pk2(bb0, 0.f), s1 = pk2(bb1, 0.f);
#pragma unroll
        for (int k2 = 0; k2 < 16; k2++) {
            unsigned long long hp = *(const unsigned long long*)&sH[r * 34 + 2 * k2];
            fma2(s0, hp, w0p[k2]);
            fma2(s1, hp, w1p[k2]);
        }
        sP[r * 514 + j0] = fmaxf(lohi(s0), 0.f);
        sP[r * 514 + j1] = fmaxf(lohi(s1), 0.f);
    }
}

// ---------------------------------------------------------------------------
// Fused heads, 32-node tile, dynamic smem (70.2KB): halves L2 weight traffic.
// h2 = relu(buf2 + b2) computed on load.
// ---------------------------------------------------------------------------
__global__ void __launch_bounds__(256) k_head(
    const float* __restrict__ b2,
    const float* __restrict__ pW1, const float* __restrict__ pb1,
    const float* __restrict__ pW2, const float* __restrict__ pb2,
    const float* __restrict__ vW1, const float* __restrict__ vb1,
    const float* __restrict__ vW2, const float* __restrict__ vb2,
    float* __restrict__ out) {
    extern __shared__ float dsm[];
    float* sH = dsm;              // 32*34   = 1088 floats
    float* sP = dsm + 32 * 34;    // 32*514  = 16448 floats
    const int t = threadIdx.x;
    const int n0 = blockIdx.x * 32;

    for (int i = t; i < 32 * 32; i += 256) {
        int r = i >> 5, c = i & 31;
        sH[r * 34 + c] = fmaxf(g_buf2[(long long)(n0 + r) * HD + c] + b2[c], 0.f);
    }
    __syncthreads();

    // ---- policy layer 1
    mlp_layer1(pW1, pb1, sH, sP, t);
    __syncthreads();

    // ---- policy layer 2: out = sP @ pW2 + pb2 (f32x2 over k)
    {
        int c = t & 31, rg = t >> 5;  // rows rg*4 .. rg*4+3
        unsigned long long a0[4], a1[4];
        unsigned long long i0 = pk2(pb2[c], 0.f), i1 = pk2(pb2[c + 32], 0.f);
#pragma unroll
        for (int i = 0; i < 4; i++) { a0[i] = i0; a1[i] = i1; }
#pragma unroll 4
        for (int k = 0; k < PD; k += 2) {
            unsigned long long w0 =
                pk2(__ldg(&pW2[k * AD + c]), __ldg(&pW2[(k + 1) * AD + c]));
            unsigned long long w1 =
                pk2(__ldg(&pW2[k * AD + 32 + c]), __ldg(&pW2[(k + 1) * AD + 32 + c]));
#pragma unroll
            for (int i = 0; i < 4; i++) {
                unsigned long long p =
                    *(const unsigned long long*)&sP[(rg * 4 + i) * 514 + k];
                fma2(a0[i], p, w0);
                fma2(a1[i], p, w1);
            }
        }
#pragma unroll
        for (int i = 0; i < 4; i++) {
            long long r = n0 + rg * 4 + i;
            out[r * AD + c] = lohi(a0[i]);
            out[r * AD + 32 + c] = lohi(a1[i]);
        }
    }
    __syncthreads();

    // ---- value layer 1
    mlp_layer1(vW1, vb1, sH, sP, t);
    __syncthreads();

    // ---- value layer 2: 8 warps x 4 rows; 8-lane strided dots + shfl reduce
    {
        int wid = t >> 5, l = t & 31;
        int row = wid * 4 + (l >> 3);
        int k0 = l & 7;
        float s = 0.f;
#pragma unroll
        for (int k = k0; k < PD; k += 8) s += sP[row * 514 + k] * __ldg(&vW2[k]);
        s += __shfl_down_sync(0xffffffffu, s, 4);
        s += __shfl_down_sync(0xffffffffu, s, 2);
        s += __shfl_down_sync(0xffffffffu, s, 1);
        if (k0 == 0) out[(long long)NN * AD + n0 + row] = s + vb2[0];
    }
}

// ---------------------------------------------------------------------------
// Host side.
// ---------------------------------------------------------------------------
extern "C" void kernel_launch(void* const* d_in, const int* in_sizes, int n_in,
                              void* d_out, int out_size) {
    const float* feat = (const float*)d_in[0];
    const int* ei = (const int*)d_in[1];  // int32 (JAX x64-off)
    const float* W1 = (const float*)d_in[2];
    const float* b1 = (const float*)d_in[3];
    const float* W2 = (const float*)d_in[4];
    const float* b2 = (const float*)d_in[5];
    const float* pW1 = (const float*)d_in[6];
    const float* pb1 = (const float*)d_in[7];
    const float* pW2 = (const float*)d_in[8];
    const float* pb2 = (const float*)d_in[9];
    const float* vW1 = (const float*)d_in[10];
    const float* vb1 = (const float*)d_in[11];
    const float* vW2 = (const float*)d_in[12];
    const float* vb2 = (const float*)d_in[13];
    float* out = (float*)d_out;

    const int* src = ei;       // edge_index[0]
    const int* dst = ei + NE;  // edge_index[1]

    static int smem_set = 0;
    const int HEAD_SMEM = (32 * 34 + 32 * 514) * 4;  // 70144 B
    if (!smem_set) {
        cudaFuncSetAttribute(k_head, cudaFuncAttributeMaxDynamicSharedMemorySize,
                             HEAD_SMEM);
        smem_set = 1;
    }

    // ---- CSR build
    k_zero<<<(NN + 255) / 256, 256>>>();
    k_hist<<<(NE + 255) / 256, 256>>>(dst);
    k_bsum<<<NB_SCAN, 256>>>();
    k_scanb<<<1, 128>>>();
    k_off<<<NB_SCAN, 1024>>>();
    k_dinv<<<(NN + 255) / 256, 256>>>();
    k_fill<<<(NE + 255) / 256, 256>>>(src, dst);

    // ---- conv1: buf1 = xs1 ; buf2 = agg1 (gather)
    k_gemm1<<<NN / 32, 256>>>(feat, W1);
    k_gather<0><<<(NN + 7) / 8, 256>>>();

    // ---- conv2: buf1 = xs2 ; buf2 = agg2 (gather)
    k_gemm2<<<(NN + 63) / 64, 256>>>(W2, b1);
    k_gather<1><<<(NN + 7) / 8, 256>>>();

    // ---- heads (reads relu(buf2 + b2))
    k_head<<<NN / 32, 256, HEAD_SMEM>>>(b2, pW1, pb1, pW2, pb2, vW1, vb1, vW2,
                                        vb2, out);
}

// round 11
// speedup vs baseline: 2.1820x; 1.0508x over previous
#include <cuda_runtime.h>

#define NN 100000
#define NE 1600000
#define FI 256
#define HD 32
#define AD 64
#define PD 512

// Scratch (device globals; no allocation allowed)
__device__ float g_buf1[NN * HD];
__device__ float g_buf2[NN * HD];
__device__ float g_dinv[NN];
__device__ int g_degi[NN];
__device__ int g_off[NN];
__device__ int g_cur[NN];
__device__ int g_csr[NE];
__device__ int g_bsum[128];
__device__ int g_boff[128];

#define NB_SCAN 98  // ceil(100000/1024)

typedef unsigned long long u64;

// ---- packed f32x2 helpers (FFMA2: 2 fp32 MACs per issue; PTX-only) -------
__device__ __forceinline__ u64 pk2(float lo, float hi) {
    u64 r;
    asm("mov.b64 %0, {%1, %2};" : "=l"(r) : "f"(lo), "f"(hi));
    return r;
}
__device__ __forceinline__ void fma2(u64& d, u64 a, u64 b) {
    asm("fma.rn.f32x2 %0, %1, %2, %0;" : "+l"(d) : "l"(a), "l"(b));
}
__device__ __forceinline__ float lohi(u64 v) {
    float lo, hi;
    asm("mov.b64 {%0, %1}, %2;" : "=f"(lo), "=f"(hi) : "l"(v));
    return lo + hi;
}

// ============================ CSR construction =============================
__global__ void k_zero() {
    int i = blockIdx.x * blockDim.x + threadIdx.x;
    if (i < NN) g_degi[i] = 0;
}

__global__ void k_hist(const int* __restrict__ dst) {
    int i = blockIdx.x * blockDim.x + threadIdx.x;
    if (i < NE) atomicAdd(&g_degi[dst[i]], 1);
}

__global__ void k_bsum() {
    __shared__ int sh[256];
    int b = blockIdx.x, t = threadIdx.x;
    int s = 0;
#pragma unroll
    for (int j = 0; j < 4; j++) {
        int i = b * 1024 + t + j * 256;
        if (i < NN) s += g_degi[i];
    }
    sh[t] = s;
    __syncthreads();
    for (int o = 128; o > 0; o >>= 1) {
        if (t < o) sh[t] += sh[t + o];
        __syncthreads();
    }
    if (t == 0) g_bsum[b] = sh[0];
}

__global__ void k_scanb() {
    __shared__ int sh[128];
    int t = threadIdx.x;
    int v = (t < NB_SCAN) ? g_bsum[t] : 0;
    sh[t] = v;
    __syncthreads();
#pragma unroll
    for (int o = 1; o < 128; o <<= 1) {
        int x = (t >= o) ? sh[t - o] : 0;
        __syncthreads();
        sh[t] += x;
        __syncthreads();
    }
    if (t < NB_SCAN) g_boff[t] = sh[t] - v;
}

__global__ void k_off() {
    __shared__ int sh[1024];
    int b = blockIdx.x, t = threadIdx.x;
    int i = b * 1024 + t;
    int v = (i < NN) ? g_degi[i] : 0;
    sh[t] = v;
    __syncthreads();
#pragma unroll
    for (int o = 1; o < 1024; o <<= 1) {
        int x = (t >= o) ? sh[t - o] : 0;
        __syncthreads();
        sh[t] += x;
        __syncthreads();
    }
    if (i < NN) {
        int off = g_boff[b] + sh[t] - v;
        g_off[i] = off;
        g_cur[i] = off;
    }
}

__global__ void k_dinv() {
    int i = blockIdx.x * blockDim.x + threadIdx.x;
    if (i < NN) g_dinv[i] = rsqrtf((float)g_degi[i] + 1.0f);  // +1 self loop
}

__global__ void k_fill(const int* __restrict__ src, const int* __restrict__ dst) {
    int i = blockIdx.x * blockDim.x + threadIdx.x;
    if (i < NE) {
        int pos = atomicAdd(&g_cur[dst[i]], 1);
        g_csr[pos] = src[i];
    }
}

// ---------------------------------------------------------------------------
// GEMM1: buf1 = (features @ W1) * dinv   (pre-scaled xs1)
// f32x2 packed: W1 k-pairs pre-packed in smem (u64), feature pairs come free
// from float4 halves. 512 FFMA2/thread (was 1024 FFMA).
// ---------------------------------------------------------------------------
__global__ void __launch_bounds__(256) k_gemm1(const float* __restrict__ feat,
                                               const float* __restrict__ W1) {
    __shared__ u64 sWp[(FI / 2) * HD];  // 128x32 u64 = 32KB
    __shared__ float sF[32 * 68];       // 8.7KB
    int t = threadIdx.x;
    // pack W1 pairs: sWp[k2*32+c] = (W1[2k2][c], W1[2k2+1][c])
    for (int idx = t; idx < (FI / 2) * HD; idx += 256) {
        int k2 = idx >> 5, c = idx & 31;
        sWp[idx] = pk2(__ldg(&W1[(2 * k2) * HD + c]), __ldg(&W1[(2 * k2 + 1) * HD + c]));
    }

    long long row0 = (long long)blockIdx.x * 32;
    int c = t & 31, rg = t >> 5;
    u64 A0 = 0, A1 = 0, A2 = 0, A3 = 0;  // (0.0, 0.0) packed

#pragma unroll
    for (int ch = 0; ch < 4; ch++) {
        __syncthreads();
#pragma unroll
        for (int u = 0; u < 2; u++) {
            int f = t + u * 256;
            int r = f >> 4, c4 = (f & 15) * 4;
            float4 v = __ldg((const float4*)(feat + (row0 + r) * FI + ch * 64 + c4));
            *(float4*)&sF[r * 68 + c4] = v;
        }
        __syncthreads();
#pragma unroll 4
        for (int k = 0; k < 64; k += 4) {
            float4 fa = *(const float4*)&sF[rg * 68 + k];
            float4 fb = *(const float4*)&sF[(rg + 8) * 68 + k];
            float4 fc = *(const float4*)&sF[(rg + 16) * 68 + k];
            float4 fd = *(const float4*)&sF[(rg + 24) * 68 + k];
            int kg2 = (ch * 64 + k) >> 1;
            u64 wA = sWp[kg2 * HD + c];
            u64 wB = sWp[(kg2 + 1) * HD + c];
            fma2(A0, pk2(fa.x, fa.y), wA);
            fma2(A0, pk2(fa.z, fa.w), wB);
            fma2(A1, pk2(fb.x, fb.y), wA);
            fma2(A1, pk2(fb.z, fb.w), wB);
            fma2(A2, pk2(fc.x, fc.y), wA);
            fma2(A2, pk2(fc.z, fc.w), wB);
            fma2(A3, pk2(fd.x, fd.y), wA);
            fma2(A3, pk2(fd.z, fd.w), wB);
        }
    }
    float d0 = g_dinv[row0 + rg], d1 = g_dinv[row0 + rg + 8];
    float d2 = g_dinv[row0 + rg + 16], d3 = g_dinv[row0 + rg + 24];
    float* o = g_buf1 + row0 * HD;
    o[(rg) * HD + c] = lohi(A0) * d0;
    o[(rg + 8) * HD + c] = lohi(A1) * d1;
    o[(rg + 16) * HD + c] = lohi(A2) * d2;
    o[(rg + 24) * HD + c] = lohi(A3) * d3;
}

// ---------------------------------------------------------------------------
// Gather aggregation (NO atomics): one warp per node, lane = feature col.
// agg[n] = dinv[n] * ( xs[n] + sum_{s in N(n)} xs[s] )
// ---------------------------------------------------------------------------
__global__ void __launch_bounds__(256) k_gather() {
    const float* xs = g_buf1;
    float* agg = g_buf2;
    int node = blockIdx.x * 8 + (threadIdx.x >> 5);
    if (node >= NN) return;
    int c = threadIdx.x & 31;
    int off = g_off[node];
    int cnt = g_degi[node];
    float acc = xs[(long long)node * HD + c];
#pragma unroll 4
    for (int j = 0; j < cnt; j++) {
        int s = __ldg(&g_csr[off + j]);            // warp-broadcast load
        acc += __ldg(&xs[(long long)s * HD + c]);  // coalesced 128B row
    }
    agg[(long long)node * HD + c] = acc * g_dinv[node];
}

// ---------------------------------------------------------------------------
// GEMM2: x2 = relu(agg1 + b1) @ W2 ; buf1 = x2 * dinv (xs2)
// ---------------------------------------------------------------------------
__global__ void __launch_bounds__(256) k_gemm2(const float* __restrict__ W2,
                                               const float* __restrict__ b1) {
    __shared__ float sW[HD * HD];
    __shared__ float sH[64 * 33];
    int t = threadIdx.x;
    for (int i = t; i < HD * HD; i += 256) sW[i] = W2[i];
    int row0 = blockIdx.x * 64;
    for (int i = t; i < 64 * 32; i += 256) {
        int r = i >> 5, c = i & 31;
        int gr = row0 + r;
        sH[r * 33 + c] = (gr < NN) ? fmaxf(g_buf2[(long long)gr * HD + c] + b1[c], 0.f) : 0.f;
    }
    __syncthreads();
    int c = t & 31, rg = t >> 5;
    float acc[8];
#pragma unroll
    for (int i = 0; i < 8; i++) acc[i] = 0.f;
#pragma unroll
    for (int k = 0; k < HD; k++) {
        float w = sW[k * HD + c];
#pragma unroll
        for (int i = 0; i < 8; i++) acc[i] += sH[(rg + 8 * i) * 33 + k] * w;
    }
#pragma unroll
    for (int i = 0; i < 8; i++) {
        int gr = row0 + rg + 8 * i;
        if (gr < NN) g_buf1[(long long)gr * HD + c] = acc[i] * g_dinv[gr];
    }
}

// ---------------------------------------------------------------------------
// Head layer 1 (policy/value shared): sP = relu(sH @ W + b), f32x2 packed.
// ---------------------------------------------------------------------------
__device__ __forceinline__ void mlp_layer1(const float* __restrict__ W,
                                           const float* __restrict__ b,
                                           const float* sH, float* sP, int t) {
    const int j0 = t, j1 = t + 256;
    u64 w0p[16], w1p[16];
#pragma unroll
    for (int k2 = 0; k2 < 16; k2++) {
        w0p[k2] = pk2(__ldg(&W[(2 * k2) * PD + j0]), __ldg(&W[(2 * k2 + 1) * PD + j0]));
        w1p[k2] = pk2(__ldg(&W[(2 * k2) * PD + j1]), __ldg(&W[(2 * k2 + 1) * PD + j1]));
    }
    float bb0 = b[j0], bb1 = b[j1];
#pragma unroll 2
    for (int r = 0; r < 32; r++) {
        u64 s0 = pk2(bb0, 0.f), s1 = pk2(bb1, 0.f);
#pragma unroll
        for (int k2 = 0; k2 < 16; k2++) {
            u64 hp = *(const u64*)&sH[r * 34 + 2 * k2];
            fma2(s0, hp, w0p[k2]);
            fma2(s1, hp, w1p[k2]);
        }
        sP[r * 514 + j0] = fmaxf(lohi(s0), 0.f);
        sP[r * 514 + j1] = fmaxf(lohi(s1), 0.f);
    }
}

// ---------------------------------------------------------------------------
// Fused heads, 32-node tile, dynamic smem 78.3KB.
// Policy layer 2 stages pW2 in 8KB smem chunks: one cooperative coalesced
// load per block instead of 8 per-warp LDG replays -> FMA-bound, not LSU.
// ---------------------------------------------------------------------------
__global__ void __launch_bounds__(256) k_head(
    const float* __restrict__ b2,
    const float* __restrict__ pW1, const float* __restrict__ pb1,
    const float* __restrict__ pW2, const float* __restrict__ pb2,
    const float* __restrict__ vW1, const float* __restrict__ vb1,
    const float* __restrict__ vW2, const float* __restrict__ vb2,
    float* __restrict__ out) {
    extern __shared__ float dsm[];
    float* sH = dsm;                        // 32*34   = 1088 floats
    float* sP = dsm + 32 * 34;              // 32*514  = 16448 floats
    float* sWc = dsm + 32 * 34 + 32 * 514;  // 32*64   = 2048 floats (8KB)
    const int t = threadIdx.x;
    const int n0 = blockIdx.x * 32;

    for (int i = t; i < 32 * 32; i += 256) {
        int r = i >> 5, c = i & 31;
        sH[r * 34 + c] = fmaxf(g_buf2[(long long)(n0 + r) * HD + c] + b2[c], 0.f);
    }
    __syncthreads();

    // ---- policy layer 1
    mlp_layer1(pW1, pb1, sH, sP, t);
    __syncthreads();

    // ---- policy layer 2: out = sP @ pW2 + pb2, k staged in 16 chunks of 32
    {
        int c = t & 31, rg = t >> 5;  // rows rg*4 .. rg*4+3
        u64 a0[4], a1[4];
        u64 i0 = pk2(pb2[c], 0.f), i1 = pk2(pb2[c + 32], 0.f);
#pragma unroll
        for (int i = 0; i < 4; i++) { a0[i] = i0; a1[i] = i1; }

        for (int ch = 0; ch < 16; ch++) {
            // stage pW2[ch*32 .. ch*32+32) x 64 (coalesced float4)
#pragma unroll
            for (int u = 0; u < 2; u++) {
                int f = t + u * 256;           // float4 idx 0..511
                int r = f >> 4, c4 = (f & 15) * 4;
                *(float4*)&sWc[r * 64 + c4] =
                    __ldg((const float4*)&pW2[(ch * 32 + r) * AD + c4]);
            }
            __syncthreads();
#pragma unroll
            for (int k2 = 0; k2 < 16; k2++) {
                int kk = ch * 32 + 2 * k2;
                u64 w0 = pk2(sWc[(2 * k2) * 64 + c], sWc[(2 * k2 + 1) * 64 + c]);
                u64 w1 = pk2(sWc[(2 * k2) * 64 + 32 + c], sWc[(2 * k2 + 1) * 64 + 32 + c]);
#pragma unroll
                for (int i = 0; i < 4; i++) {
                    u64 p = *(const u64*)&sP[(rg * 4 + i) * 514 + kk];
                    fma2(a0[i], p, w0);
                    fma2(a1[i], p, w1);
                }
            }
            __syncthreads();
        }
#pragma unroll
        for (int i = 0; i < 4; i++) {
            long long r = n0 + rg * 4 + i;
            out[r * AD + c] = lohi(a0[i]);
            out[r * AD + 32 + c] = lohi(a1[i]);
        }
    }
    __syncthreads();

    // ---- value layer 1
    mlp_layer1(vW1, vb1, sH, sP, t);

    // stage vW2 (512 floats) into sWc
    if (t < 128) *(float4*)&sWc[t * 4] = __ldg((const float4*)&vW2[t * 4]);
    __syncthreads();

    // ---- value layer 2: 8 warps x 4 rows; 8-lane strided dots + shfl reduce
    {
        int wid = t >> 5, l = t & 31;
        int row = wid * 4 + (l >> 3);
        int k0 = l & 7;
        float s = 0.f;
#pragma unroll
        for (int k = k0; k < PD; k += 8) s += sP[row * 514 + k] * sWc[k];
        s += __shfl_down_sync(0xffffffffu, s, 4);
        s += __shfl_down_sync(0xffffffffu, s, 2);
        s += __shfl_down_sync(0xffffffffu, s, 1);
        if (k0 == 0) out[(long long)NN * AD + n0 + row] = s + vb2[0];
    }
}

// ---------------------------------------------------------------------------
// Host side.
// ---------------------------------------------------------------------------
extern "C" void kernel_launch(void* const* d_in, const int* in_sizes, int n_in,
                              void* d_out, int out_size) {
    const float* feat = (const float*)d_in[0];
    const int* ei = (const int*)d_in[1];  // int32 (JAX x64-off)
    const float* W1 = (const float*)d_in[2];
    const float* b1 = (const float*)d_in[3];
    const float* W2 = (const float*)d_in[4];
    const float* b2 = (const float*)d_in[5];
    const float* pW1 = (const float*)d_in[6];
    const float* pb1 = (const float*)d_in[7];
    const float* pW2 = (const float*)d_in[8];
    const float* pb2 = (const float*)d_in[9];
    const float* vW1 = (const float*)d_in[10];
    const float* vb1 = (const float*)d_in[11];
    const float* vW2 = (const float*)d_in[12];
    const float* vb2 = (const float*)d_in[13];
    float* out = (float*)d_out;

    const int* src = ei;       // edge_index[0]
    const int* dst = ei + NE;  // edge_index[1]

    static int smem_set = 0;
    const int HEAD_SMEM = (32 * 34 + 32 * 514 + 32 * 64) * 4;  // 78336 B
    if (!smem_set) {
        cudaFuncSetAttribute(k_head, cudaFuncAttributeMaxDynamicSharedMemorySize,
                             HEAD_SMEM);
        smem_set = 1;
    }

    // ---- CSR build
    k_zero<<<(NN + 255) / 256, 256>>>();
    k_hist<<<(NE + 255) / 256, 256>>>(dst);
    k_bsum<<<NB_SCAN, 256>>>();
    k_scanb<<<1, 128>>>();
    k_off<<<NB_SCAN, 1024>>>();
    k_dinv<<<(NN + 255) / 256, 256>>>();
    k_fill<<<(NE + 255) / 256, 256>>>(src, dst);

    // ---- conv1: buf1 = xs1 ; buf2 = agg1 (gather)
    k_gemm1<<<NN / 32, 256>>>(feat, W1);
    k_gather<<<(NN + 7) / 8, 256>>>();

    // ---- conv2: buf1 = xs2 ; buf2 = agg2 (gather)
    k_gemm2<<<(NN + 63) / 64, 256>>>(W2, b1);
    k_gather<<<(NN + 7) / 8, 256>>>();

    // ---- heads (reads relu(buf2 + b2))
    k_head<<<NN / 32, 256, HEAD_SMEM>>>(b2, pW1, pb1, pW2, pb2, vW1, vb1, vW2,
                                        vb2, out);
}